// round 1
// baseline (speedup 1.0000x reference)
#include <cuda_runtime.h>
#include <math.h>

#define HH 160
#define WW 160
#define BB 4
#define CIN 64
#define COUT 64
#define KKK 9
#define PADK 4
#define NPIX (BB*HH*WW)      /* 102400 */
#define EPSV 1e-5f
#define NBLK_A 100           /* 25600 threads / 256 */

// ---------------- device scratch (no runtime allocation allowed) ----------------
__device__ __align__(16) float g_off9[BB*KKK*HH*WW];   // offset-conv output, odd channels only
__device__ float g_partials[NBLK_A*18];                // per-block [sum(9), sumsq(9)]
__device__ float g_scale[KKK];
__device__ float g_shift[KKK];
__device__ __align__(16) float g_wdefT[KKK*CIN*COUT];  // w_def transposed to [k][c][o]

// ---------------- kernel W: transpose w_def [o][c][k] -> [k][c][o] ----------------
__global__ void transpose_wdef_kernel(const float* __restrict__ w_def) {
    int idx = blockIdx.x*256 + threadIdx.x;
    if (idx >= COUT*CIN*KKK) return;
    int o = idx/(CIN*KKK);
    int c = (idx/KKK)%CIN;
    int k = idx%KKK;
    g_wdefT[(k*CIN + c)*COUT + o] = w_def[idx];
}

// ---------------- kernel A: offset conv (9 odd channels) + partial stats ----------------
// thread = (b, h, w4): computes 9 channels x 4 consecutive w.
__global__ __launch_bounds__(256) void offset_conv_kernel(
        const float* __restrict__ x,
        const float* __restrict__ w_off,
        const float* __restrict__ b_off) {
    __shared__ float wsm[576*12];   // [c*9+ky][ch(9) pad to 12]
    __shared__ float bo[KKK];
    __shared__ float red[8*18];

    int tid = threadIdx.x;
    for (int e = tid; e < 576*9; e += 256) {
        int j = e % 9;          // odd-channel index
        int ck = e / 9;         // c*9 + ky
        wsm[ck*12 + j] = w_off[(2*j+1)*576 + ck];
    }
    if (tid < 9) bo[tid] = b_off[2*tid+1];
    __syncthreads();

    int g  = blockIdx.x*256 + tid;
    int w4 = g % 40;
    int h  = (g/40) % HH;
    int b  = g / (40*HH);

    float4 acc[9];
#pragma unroll
    for (int j = 0; j < 9; j++) acc[j] = make_float4(bo[j], bo[j], bo[j], bo[j]);

    const float* xb = x + (size_t)b*CIN*HH*WW + w4*4;

#pragma unroll
    for (int ky = 0; ky < 9; ky++) {
        int row = h - PADK + ky;
        if ((unsigned)row >= (unsigned)HH) continue;
        const float* xr = xb + row*WW;
#pragma unroll 4
        for (int c = 0; c < CIN; c++) {
            float4 xv = *(const float4*)(xr + c*(HH*WW));
            const float* wr = &wsm[(c*9 + ky)*12];
            float4 wA = *(const float4*)wr;
            float4 wB = *(const float4*)(wr + 4);
            float  w8 = wr[8];
#define FMA4(A, S) { A.x += xv.x*(S); A.y += xv.y*(S); A.z += xv.z*(S); A.w += xv.w*(S); }
            FMA4(acc[0], wA.x); FMA4(acc[1], wA.y); FMA4(acc[2], wA.z); FMA4(acc[3], wA.w);
            FMA4(acc[4], wB.x); FMA4(acc[5], wB.y); FMA4(acc[6], wB.z); FMA4(acc[7], wB.w);
            FMA4(acc[8], w8);
#undef FMA4
        }
    }

    // store off9
#pragma unroll
    for (int j = 0; j < 9; j++) {
        *(float4*)&g_off9[((size_t)(b*9 + j)*HH + h)*WW + w4*4] = acc[j];
    }

    // stats partials (deterministic tree reduce)
    float ls[9], ls2[9];
#pragma unroll
    for (int j = 0; j < 9; j++) {
        float4 a = acc[j];
        ls[j]  = a.x + a.y + a.z + a.w;
        ls2[j] = a.x*a.x + a.y*a.y + a.z*a.z + a.w*a.w;
    }
#pragma unroll
    for (int off = 16; off > 0; off >>= 1) {
#pragma unroll
        for (int j = 0; j < 9; j++) {
            ls[j]  += __shfl_down_sync(0xffffffffu, ls[j],  off);
            ls2[j] += __shfl_down_sync(0xffffffffu, ls2[j], off);
        }
    }
    int lane = tid & 31, wid = tid >> 5;
    if (lane == 0) {
#pragma unroll
        for (int j = 0; j < 9; j++) {
            red[wid*18 + j]     = ls[j];
            red[wid*18 + 9 + j] = ls2[j];
        }
    }
    __syncthreads();
    if (tid < 18) {
        float s = 0.f;
#pragma unroll
        for (int i = 0; i < 8; i++) s += red[i*18 + tid];
        g_partials[blockIdx.x*18 + tid] = s;
    }
}

// ---------------- kernel B: finalize stats -> scale/shift ----------------
__global__ void stats_kernel(const float* __restrict__ gamma,
                             const float* __restrict__ beta) {
    __shared__ float sm[18];
    int tid = threadIdx.x;
    if (tid < 18) {
        float s = 0.f;
        for (int i = 0; i < NBLK_A; i++) s += g_partials[i*18 + tid];
        sm[tid] = s;
    }
    __syncthreads();
    if (tid < 9) {
        float mean = sm[tid] * (1.0f/(float)NPIX);
        float var  = sm[9+tid] * (1.0f/(float)NPIX) - mean*mean;
        float rstd = rsqrtf(fmaxf(var, 0.f) + EPSV);
        float sc   = rstd * gamma[2*tid+1];
        g_scale[tid] = sc;
        g_shift[tid] = beta[2*tid+1] - mean*sc;
    }
}

// ---------------- kernel C: deformable conv ----------------
// Block = (h, b). Tile: 64 outputs x 160 w. 320 threads, 8o x 4w per thread.
// Dynamic smem layout (floats):
//   s   [64*160]          samples for current k
//   wk  [64*64]           w_defT slice for current k ([c][o])
//   sw0 [9*160] sw1[9*160]   interp weights (validity folded in)
//   sx0 [9*160] sx1[9*160]   clamped gather columns (int)
#define SMEM_S    0
#define SMEM_WK   (64*WW)
#define SMEM_SW0  (SMEM_WK + 64*64)
#define SMEM_SW1  (SMEM_SW0 + 9*WW)
#define SMEM_SX0  (SMEM_SW1 + 9*WW)
#define SMEM_SX1  (SMEM_SX0 + 9*WW)
#define SMEM_TOT_ELEMS (SMEM_SX1 + 9*WW)

extern __shared__ float dsm[];

__global__ __launch_bounds__(320, 2) void deform_kernel(
        const float* __restrict__ x,
        const float* __restrict__ b_def,
        float* __restrict__ out) {
    float* s   = dsm + SMEM_S;
    float* wk  = dsm + SMEM_WK;
    float* sw0 = dsm + SMEM_SW0;
    float* sw1 = dsm + SMEM_SW1;
    int*   sx0 = (int*)(dsm + SMEM_SX0);
    int*   sx1 = (int*)(dsm + SMEM_SX1);

    int tid = threadIdx.x;
    int h = blockIdx.x;
    int b = blockIdx.y;

    // ---- phase 0: offsets (tanh + cumulative convert + interp params) ----
    if (tid < WW) {
        int w = tid;
        float y[9], dx[9];
#pragma unroll
        for (int k = 0; k < 9; k++) {
            float v = g_off9[((size_t)(b*9 + k)*HH + h)*WW + w];
            y[k] = tanhf(v*g_scale[k] + g_shift[k]);
        }
        dx[4] = y[4];
        float a = y[4];
#pragma unroll
        for (int k = 3; k >= 0; k--) { a += y[k]; dx[k] = a; }
        a = y[4];
#pragma unroll
        for (int k = 5; k < 9; k++) { a += y[k]; dx[k] = a; }
#pragma unroll
        for (int k = 0; k < 9; k++) {
            float px = (float)w + dx[k];
            float fl = floorf(px);
            float fx = px - fl;
            int   x0 = (int)fl;
            sw0[k*WW + w] = (x0 >= 0 && x0 < WW)       ? (1.f - fx) : 0.f;
            sw1[k*WW + w] = (x0 >= -1 && x0 < WW - 1)  ? fx         : 0.f;
            sx0[k*WW + w] = min(max(x0, 0), WW - 1);
            sx1[k*WW + w] = min(max(x0 + 1, 0), WW - 1);
        }
    }

    const int og = tid / 40;   // 0..7  -> outputs og*8 .. og*8+7
    const int wg = tid % 40;   // 0..39 -> w = wg*4 .. wg*4+3
    float4 acc[8];
#pragma unroll
    for (int i = 0; i < 8; i++) acc[i] = make_float4(0.f, 0.f, 0.f, 0.f);

    const float* xbatch = x + (size_t)b*CIN*HH*WW;

    for (int k = 0; k < 9; k++) {
        int row = h - PADK + k;
        if ((unsigned)row >= (unsigned)HH) continue;   // uniform across block
        __syncthreads();  // also serves as the phase-0 barrier on first valid k

        // load w_defT slice for this k
        {
            const float4* wsrc = (const float4*)(g_wdefT + (size_t)k*CIN*COUT);
            float4* wk4 = (float4*)wk;
            for (int i = tid; i < CIN*COUT/4; i += 320) wk4[i] = wsrc[i];
        }
        // gather + interpolate samples s[c][w]
        {
            const float* xrow = xbatch + (size_t)row*WW;
            for (int i = tid; i < CIN*WW; i += 320) {
                int c = i / WW;
                int w = i - c*WW;
                const float* xr = xrow + (size_t)c*HH*WW;
                int oidx = k*WW + w;
                s[i] = sw0[oidx]*__ldg(xr + sx0[oidx]) + sw1[oidx]*__ldg(xr + sx1[oidx]);
            }
        }
        __syncthreads();

        // accumulate: out[o][w] += sum_c wk[c][o] * s[c][w]
#pragma unroll 4
        for (int c = 0; c < CIN; c++) {
            float4 sv = *(const float4*)&s[c*WW + wg*4];
            const float4* wr = (const float4*)&wk[c*COUT];
            float4 w0v = wr[og*2];
            float4 w1v = wr[og*2 + 1];
#define ACC4(I, S) { acc[I].x += (S)*sv.x; acc[I].y += (S)*sv.y; acc[I].z += (S)*sv.z; acc[I].w += (S)*sv.w; }
            ACC4(0, w0v.x); ACC4(1, w0v.y); ACC4(2, w0v.z); ACC4(3, w0v.w);
            ACC4(4, w1v.x); ACC4(5, w1v.y); ACC4(6, w1v.z); ACC4(7, w1v.w);
#undef ACC4
        }
    }

    // epilogue: add bias, write out
#pragma unroll
    for (int oi = 0; oi < 8; oi++) {
        int o = og*8 + oi;
        float bv = __ldg(&b_def[o]);
        float4 r = acc[oi];
        r.x += bv; r.y += bv; r.z += bv; r.w += bv;
        *(float4*)&out[(((size_t)b*COUT + o)*HH + h)*WW + wg*4] = r;
    }
}

// ---------------- launch ----------------
extern "C" void kernel_launch(void* const* d_in, const int* in_sizes, int n_in,
                              void* d_out, int out_size) {
    const float* x     = (const float*)d_in[0];
    const float* w_off = (const float*)d_in[1];
    const float* b_off = (const float*)d_in[2];
    const float* gamma = (const float*)d_in[3];
    const float* beta  = (const float*)d_in[4];
    const float* w_def = (const float*)d_in[5];
    const float* b_def = (const float*)d_in[6];
    float* out = (float*)d_out;

    static bool attr_set = false;
    if (!attr_set) {
        cudaFuncSetAttribute(deform_kernel,
                             cudaFuncAttributeMaxDynamicSharedMemorySize,
                             SMEM_TOT_ELEMS * (int)sizeof(float));
        attr_set = true;
    }

    transpose_wdef_kernel<<<(COUT*CIN*KKK + 255)/256, 256>>>(w_def);
    offset_conv_kernel<<<NBLK_A, 256>>>(x, w_off, b_off);
    stats_kernel<<<1, 32>>>(gamma, beta);
    deform_kernel<<<dim3(HH, BB), 320, SMEM_TOT_ELEMS * (int)sizeof(float)>>>(x, b_def, out);
}

// round 2
// speedup vs baseline: 1.5914x; 1.5914x over previous
#include <cuda_runtime.h>
#include <math.h>

#define HH 160
#define WW 160
#define BB 4
#define CIN 64
#define COUT 64
#define KKK 9
#define PADK 4
#define NPIX (BB*HH*WW)      /* 102400 */
#define EPSV 1e-5f
#define NBLK_A 100           /* 25600 threads / 256 */

// ---------------- device scratch (no runtime allocation allowed) ----------------
__device__ __align__(16) float g_off9[BB*KKK*HH*WW];   // offset-conv output, odd channels only
__device__ float g_partials[NBLK_A*18];                // per-block [sum(9), sumsq(9)]
__device__ float g_scale[KKK];
__device__ float g_shift[KKK];
__device__ __align__(16) float g_wdefT[KKK*CIN*COUT];  // w_def transposed to [k][c][o]

// ---------------- packed f32x2 helpers ----------------
__device__ __forceinline__ unsigned long long pack2(float v) {
    unsigned long long r;
    asm("mov.b64 %0, {%1, %1};" : "=l"(r) : "f"(v));
    return r;
}
__device__ __forceinline__ unsigned long long fma2(unsigned long long a,
                                                   unsigned long long b,
                                                   unsigned long long c) {
    unsigned long long d;
    asm("fma.rn.f32x2 %0, %1, %2, %3;" : "=l"(d) : "l"(a), "l"(b), "l"(c));
    return d;
}
__device__ __forceinline__ float2 unpack2(unsigned long long v) {
    float2 f;
    asm("mov.b64 {%0, %1}, %2;" : "=f"(f.x), "=f"(f.y) : "l"(v));
    return f;
}

// ---------------- kernel W: transpose w_def [o][c][k] -> [k][c][o] ----------------
__global__ void transpose_wdef_kernel(const float* __restrict__ w_def) {
    int idx = blockIdx.x*256 + threadIdx.x;
    if (idx >= COUT*CIN*KKK) return;
    int o = idx/(CIN*KKK);
    int c = (idx/KKK)%CIN;
    int k = idx%KKK;
    g_wdefT[(k*CIN + c)*COUT + o] = w_def[idx];
}

// ---------------- kernel A: offset conv (9 odd channels) + partial stats ----------------
__global__ __launch_bounds__(256) void offset_conv_kernel(
        const float* __restrict__ x,
        const float* __restrict__ w_off,
        const float* __restrict__ b_off) {
    __shared__ float wsm[576*12];   // [c*9+ky][ch(9) pad to 12]
    __shared__ float bo[KKK];
    __shared__ float red[8*18];

    int tid = threadIdx.x;
    for (int e = tid; e < 576*9; e += 256) {
        int j = e % 9;          // odd-channel index
        int ck = e / 9;         // c*9 + ky
        wsm[ck*12 + j] = w_off[(2*j+1)*576 + ck];
    }
    if (tid < 9) bo[tid] = b_off[2*tid+1];
    __syncthreads();

    int g  = blockIdx.x*256 + tid;
    int w4 = g % 40;
    int h  = (g/40) % HH;
    int b  = g / (40*HH);

    float4 acc[9];
#pragma unroll
    for (int j = 0; j < 9; j++) acc[j] = make_float4(bo[j], bo[j], bo[j], bo[j]);

    const float* xb = x + (size_t)b*CIN*HH*WW + w4*4;

#pragma unroll
    for (int ky = 0; ky < 9; ky++) {
        int row = h - PADK + ky;
        if ((unsigned)row >= (unsigned)HH) continue;
        const float* xr = xb + row*WW;
#pragma unroll 4
        for (int c = 0; c < CIN; c++) {
            float4 xv = *(const float4*)(xr + c*(HH*WW));
            const float* wr = &wsm[(c*9 + ky)*12];
            float4 wA = *(const float4*)wr;
            float4 wB = *(const float4*)(wr + 4);
            float  w8 = wr[8];
#define FMA4(A, S) { A.x += xv.x*(S); A.y += xv.y*(S); A.z += xv.z*(S); A.w += xv.w*(S); }
            FMA4(acc[0], wA.x); FMA4(acc[1], wA.y); FMA4(acc[2], wA.z); FMA4(acc[3], wA.w);
            FMA4(acc[4], wB.x); FMA4(acc[5], wB.y); FMA4(acc[6], wB.z); FMA4(acc[7], wB.w);
            FMA4(acc[8], w8);
#undef FMA4
        }
    }

    // store off9
#pragma unroll
    for (int j = 0; j < 9; j++) {
        *(float4*)&g_off9[((size_t)(b*9 + j)*HH + h)*WW + w4*4] = acc[j];
    }

    // stats partials (deterministic tree reduce)
    float ls[9], ls2[9];
#pragma unroll
    for (int j = 0; j < 9; j++) {
        float4 a = acc[j];
        ls[j]  = a.x + a.y + a.z + a.w;
        ls2[j] = a.x*a.x + a.y*a.y + a.z*a.z + a.w*a.w;
    }
#pragma unroll
    for (int off = 16; off > 0; off >>= 1) {
#pragma unroll
        for (int j = 0; j < 9; j++) {
            ls[j]  += __shfl_down_sync(0xffffffffu, ls[j],  off);
            ls2[j] += __shfl_down_sync(0xffffffffu, ls2[j], off);
        }
    }
    int lane = tid & 31, wid = tid >> 5;
    if (lane == 0) {
#pragma unroll
        for (int j = 0; j < 9; j++) {
            red[wid*18 + j]     = ls[j];
            red[wid*18 + 9 + j] = ls2[j];
        }
    }
    __syncthreads();
    if (tid < 18) {
        float s = 0.f;
#pragma unroll
        for (int i = 0; i < 8; i++) s += red[i*18 + tid];
        g_partials[blockIdx.x*18 + tid] = s;
    }
}

// ---------------- kernel B: finalize stats -> scale/shift ----------------
__global__ void stats_kernel(const float* __restrict__ gamma,
                             const float* __restrict__ beta) {
    __shared__ float sm[18];
    int tid = threadIdx.x;
    if (tid < 18) {
        float s = 0.f;
        for (int i = 0; i < NBLK_A; i++) s += g_partials[i*18 + tid];
        sm[tid] = s;
    }
    __syncthreads();
    if (tid < 9) {
        float mean = sm[tid] * (1.0f/(float)NPIX);
        float var  = sm[9+tid] * (1.0f/(float)NPIX) - mean*mean;
        float rstd = rsqrtf(fmaxf(var, 0.f) + EPSV);
        float sc   = rstd * gamma[2*tid+1];
        g_scale[tid] = sc;
        g_shift[tid] = beta[2*tid+1] - mean*sc;
    }
}

// ---------------- kernel C: deformable conv (f32x2 packed) ----------------
// Block = (h, b). Tile: 64 outputs x 160 w. 320 threads, 8o x 4w per thread.
// Accumulators packed as o-pairs: acc[p][j] = (out[og*8+2p], out[og*8+2p+1]) at w=wg*4+j.
#define SMEM_S    0
#define SMEM_WK   (64*WW)
#define SMEM_SW0  (SMEM_WK + 64*64)
#define SMEM_SW1  (SMEM_SW0 + 9*WW)
#define SMEM_SX0  (SMEM_SW1 + 9*WW)
#define SMEM_SX1  (SMEM_SX0 + 9*WW)
#define SMEM_TOT_ELEMS (SMEM_SX1 + 9*WW)

extern __shared__ float dsm[];

__global__ __launch_bounds__(320, 2) void deform_kernel(
        const float* __restrict__ x,
        const float* __restrict__ b_def,
        float* __restrict__ out) {
    float* s   = dsm + SMEM_S;
    float* wk  = dsm + SMEM_WK;
    float* sw0 = dsm + SMEM_SW0;
    float* sw1 = dsm + SMEM_SW1;
    int*   sx0 = (int*)(dsm + SMEM_SX0);
    int*   sx1 = (int*)(dsm + SMEM_SX1);

    int tid = threadIdx.x;
    int h = blockIdx.x;
    int b = blockIdx.y;

    // ---- phase 0: offsets (tanh + cumulative convert + interp params) ----
    if (tid < WW) {
        int w = tid;
        float y[9], dx[9];
#pragma unroll
        for (int k = 0; k < 9; k++) {
            float v = g_off9[((size_t)(b*9 + k)*HH + h)*WW + w];
            y[k] = tanhf(v*g_scale[k] + g_shift[k]);
        }
        dx[4] = y[4];
        float a = y[4];
#pragma unroll
        for (int k = 3; k >= 0; k--) { a += y[k]; dx[k] = a; }
        a = y[4];
#pragma unroll
        for (int k = 5; k < 9; k++) { a += y[k]; dx[k] = a; }
#pragma unroll
        for (int k = 0; k < 9; k++) {
            float px = (float)w + dx[k];
            float fl = floorf(px);
            float fx = px - fl;
            int   x0 = (int)fl;
            sw0[k*WW + w] = (x0 >= 0 && x0 < WW)       ? (1.f - fx) : 0.f;
            sw1[k*WW + w] = (x0 >= -1 && x0 < WW - 1)  ? fx         : 0.f;
            sx0[k*WW + w] = min(max(x0, 0), WW - 1);
            sx1[k*WW + w] = min(max(x0 + 1, 0), WW - 1);
        }
    }

    const int og = tid / 40;   // 0..7  -> outputs og*8 .. og*8+7
    const int wg = tid % 40;   // 0..39 -> w = wg*4 .. wg*4+3

    unsigned long long acc[4][4];
#pragma unroll
    for (int p = 0; p < 4; p++)
#pragma unroll
        for (int j = 0; j < 4; j++) acc[p][j] = 0ull;

    const float* xbatch = x + (size_t)b*CIN*HH*WW;
    const int gw = tid % WW;        // gather column for this thread (0..159)
    const int gc = tid / WW;        // gather channel start (0 or 1)

    for (int k = 0; k < 9; k++) {
        int row = h - PADK + k;
        if ((unsigned)row >= (unsigned)HH) continue;   // uniform across block
        __syncthreads();  // also serves as the phase-0 barrier on first valid k

        // load w_defT slice for this k
        {
            const float4* wsrc = (const float4*)(g_wdefT + (size_t)k*CIN*COUT);
            float4* wk4 = (float4*)wk;
            for (int i = tid; i < CIN*COUT/4; i += 320) wk4[i] = wsrc[i];
        }
        // gather + interpolate samples s[c][w]; fixed w per thread, stride 2 over c
        {
            const float* xrow = xbatch + (size_t)row*WW;
            int oidx = k*WW + gw;
            float iw0 = sw0[oidx];
            float iw1 = sw1[oidx];
            const float* p0 = xrow + sx0[oidx];
            const float* p1 = xrow + sx1[oidx];
#pragma unroll 8
            for (int c = gc; c < CIN; c += 2) {
                s[c*WW + gw] = iw0*__ldg(p0 + c*(HH*WW)) + iw1*__ldg(p1 + c*(HH*WW));
            }
        }
        __syncthreads();

        // accumulate: out[o][w] += sum_c wk[c][o] * s[c][w]   (f32x2 over o-pairs)
#pragma unroll 4
        for (int c = 0; c < CIN; c++) {
            float4 sv = *(const float4*)&s[c*WW + wg*4];
            unsigned long long s0 = pack2(sv.x);
            unsigned long long s1 = pack2(sv.y);
            unsigned long long s2 = pack2(sv.z);
            unsigned long long s3 = pack2(sv.w);
            const ulonglong2* wr = (const ulonglong2*)&wk[c*COUT + og*8];
            ulonglong2 wA = wr[0];  // pairs (o0,o1),(o2,o3)
            ulonglong2 wB = wr[1];  // pairs (o4,o5),(o6,o7)
            acc[0][0] = fma2(wA.x, s0, acc[0][0]);
            acc[0][1] = fma2(wA.x, s1, acc[0][1]);
            acc[0][2] = fma2(wA.x, s2, acc[0][2]);
            acc[0][3] = fma2(wA.x, s3, acc[0][3]);
            acc[1][0] = fma2(wA.y, s0, acc[1][0]);
            acc[1][1] = fma2(wA.y, s1, acc[1][1]);
            acc[1][2] = fma2(wA.y, s2, acc[1][2]);
            acc[1][3] = fma2(wA.y, s3, acc[1][3]);
            acc[2][0] = fma2(wB.x, s0, acc[2][0]);
            acc[2][1] = fma2(wB.x, s1, acc[2][1]);
            acc[2][2] = fma2(wB.x, s2, acc[2][2]);
            acc[2][3] = fma2(wB.x, s3, acc[2][3]);
            acc[3][0] = fma2(wB.y, s0, acc[3][0]);
            acc[3][1] = fma2(wB.y, s1, acc[3][1]);
            acc[3][2] = fma2(wB.y, s2, acc[3][2]);
            acc[3][3] = fma2(wB.y, s3, acc[3][3]);
        }
    }

    // epilogue: unpack o-pairs, add bias, write out (float4 per output row)
#pragma unroll
    for (int p = 0; p < 4; p++) {
        int o0 = og*8 + 2*p;
        float bv0 = __ldg(&b_def[o0]);
        float bv1 = __ldg(&b_def[o0+1]);
        float2 f0 = unpack2(acc[p][0]);
        float2 f1 = unpack2(acc[p][1]);
        float2 f2 = unpack2(acc[p][2]);
        float2 f3 = unpack2(acc[p][3]);
        float4 r0 = make_float4(f0.x + bv0, f1.x + bv0, f2.x + bv0, f3.x + bv0);
        float4 r1 = make_float4(f0.y + bv1, f1.y + bv1, f2.y + bv1, f3.y + bv1);
        *(float4*)&out[(((size_t)b*COUT + o0  )*HH + h)*WW + wg*4] = r0;
        *(float4*)&out[(((size_t)b*COUT + o0+1)*HH + h)*WW + wg*4] = r1;
    }
}

// ---------------- launch ----------------
extern "C" void kernel_launch(void* const* d_in, const int* in_sizes, int n_in,
                              void* d_out, int out_size) {
    const float* x     = (const float*)d_in[0];
    const float* w_off = (const float*)d_in[1];
    const float* b_off = (const float*)d_in[2];
    const float* gamma = (const float*)d_in[3];
    const float* beta  = (const float*)d_in[4];
    const float* w_def = (const float*)d_in[5];
    const float* b_def = (const float*)d_in[6];
    float* out = (float*)d_out;

    static bool attr_set = false;
    if (!attr_set) {
        cudaFuncSetAttribute(deform_kernel,
                             cudaFuncAttributeMaxDynamicSharedMemorySize,
                             SMEM_TOT_ELEMS * (int)sizeof(float));
        attr_set = true;
    }

    transpose_wdef_kernel<<<(COUT*CIN*KKK + 255)/256, 256>>>(w_def);
    offset_conv_kernel<<<NBLK_A, 256>>>(x, w_off, b_off);
    stats_kernel<<<1, 32>>>(gamma, beta);
    deform_kernel<<<dim3(HH, BB), 320, SMEM_TOT_ELEMS * (int)sizeof(float)>>>(x, b_def, out);
}